// round 2
// baseline (speedup 1.0000x reference)
#include <cuda_runtime.h>
#include <cstdint>

// Problem constants (IcoGenericUpConv: ico order 5 -> 6)
#define BB      16
#define C_INX   256
#define C_OUTX  128
#define N_LOW   10242
#define N_UP    40962
#define KNEIGH  7
#define KF      (KNEIGH * C_OUTX)   // 896

// Tiling
#define TM      128                 // vertices per block tile
#define TN      128                 // = C_OUT (one neighbor group at a time)
#define KC      64                  // K-chunk for weight staging
#define NTHREADS 256
#define VTILES  81                  // ceil(10242/128)

// Dynamic smem: Xs[256][128] + Ws[64][128]
#define XS_ELEMS (C_INX * TM)
#define WS_ELEMS (KC * TN)
#define SMEM_BYTES ((XS_ELEMS + WS_ELEMS) * sizeof(float))

// reciprocal segment counts (recomputed every launch -> deterministic)
__device__ float g_inv[N_UP];

// ---------------------------------------------------------------------------
// packed f32x2 helpers (Blackwell FFMA2)
// ---------------------------------------------------------------------------
__device__ __forceinline__ unsigned long long pack2(float lo, float hi) {
    unsigned long long r;
    asm("mov.b64 %0, {%1, %2};" : "=l"(r) : "f"(lo), "f"(hi));
    return r;
}
__device__ __forceinline__ void fma2(unsigned long long& d,
                                     unsigned long long a,
                                     unsigned long long b) {
    asm("fma.rn.f32x2 %0, %1, %2, %3;" : "=l"(d) : "l"(a), "l"(b), "l"(d));
}
__device__ __forceinline__ void unpack2(unsigned long long v, float& lo, float& hi) {
    asm("mov.b64 {%0, %1}, %2;" : "=f"(lo), "=f"(hi) : "l"(v));
}

// ---------------------------------------------------------------------------
// count / invert kernels
// ---------------------------------------------------------------------------
__global__ void zero_counts_k() {
    int i = blockIdx.x * blockDim.x + threadIdx.x;
    if (i < N_UP) g_inv[i] = 0.0f;
}

__global__ void count_k(const int* __restrict__ neigh) {
    int i = blockIdx.x * blockDim.x + threadIdx.x;
    if (i < N_LOW * KNEIGH) atomicAdd(&g_inv[neigh[i]], 1.0f);
}

__global__ void invert_k() {
    int i = blockIdx.x * blockDim.x + threadIdx.x;
    if (i < N_UP) g_inv[i] = 1.0f / g_inv[i];   // every segment covered >= once
}

// ---------------------------------------------------------------------------
// Fused GEMM + segment-mean scatter
//   block = (v-tile of 128, batch b); loops neighbor groups kg=0..6 reusing
//   the SMEM x tile; scatters (acc + bias)*inv_count via atomicAdd.
// ---------------------------------------------------------------------------
__global__ __launch_bounds__(NTHREADS, 1)
void fused_gemm_scatter_k(const float* __restrict__ x,
                          const float* __restrict__ w,
                          const float* __restrict__ bias,
                          const int*   __restrict__ neigh,
                          float*       __restrict__ out)
{
    extern __shared__ float sm[];
    float* Xs = sm;                  // [C_INX][TM]
    float* Ws = sm + XS_ELEMS;       // [KC][TN]
    __shared__ int   u_s[TM];
    __shared__ float sc_s[TM];
    __shared__ float b_s[TN];

    const int v0  = blockIdx.x * TM;
    const int b   = blockIdx.y;
    const int tid = threadIdx.x;

    // ---- load X tile: Xs[c][v] for c in [0,256), v in [0,128) ----
    {
        const float* xb = x + (size_t)b * C_INX * N_LOW;
        const int lane  = tid & 63;      // 64 float2 per c-row
        const int c0    = tid >> 6;      // 0..3
        const int v     = lane * 2;
        const int gv    = v0 + v;
        for (int c = c0; c < C_INX; c += 4) {
            float2 val = make_float2(0.0f, 0.0f);
            if (gv + 1 < N_LOW) {
                val = *(const float2*)(xb + (size_t)c * N_LOW + gv);
            } else if (gv < N_LOW) {
                val.x = xb[(size_t)c * N_LOW + gv];
            }
            *(float2*)&Xs[c * TM + v] = val;
        }
    }

    const int tm = tid >> 4;       // 0..15 -> rows r0..r0+7
    const int tn = tid & 15;       // 0..15 -> cols tn + 16*j
    const int r0 = tm * 8;

    float* ob = out + (size_t)b * C_OUTX * N_UP;

    for (int kg = 0; kg < KNEIGH; ++kg) {
        // acc[i][j] packs rows (r0+2i, r0+2i+1), column tn+16*j
        unsigned long long acc[4][8];
#pragma unroll
        for (int i = 0; i < 4; ++i)
#pragma unroll
            for (int j = 0; j < 8; ++j) acc[i][j] = 0ULL;

        for (int ch = 0; ch < C_INX / KC; ++ch) {
            __syncthreads();  // Ws reusable; also covers initial Xs fill
            // ---- stage W chunk: Ws[cc][n], cc in [0,64), n in [0,128) ----
            {
                const float* wg = w + (size_t)(ch * KC) * KF + kg * C_OUTX;
#pragma unroll
                for (int it = 0; it < 8; ++it) {
                    int idx = it * 256 + tid;         // 2048 float4 total
                    int cc  = idx >> 5;               // 32 float4 per row
                    int n4  = (idx & 31) * 4;
                    float4 v = *(const float4*)(wg + (size_t)cc * KF + n4);
                    *(float4*)&Ws[cc * TN + n4] = v;
                }
            }
            __syncthreads();

            // ---- inner product over this K chunk ----
#pragma unroll 4
            for (int cc = 0; cc < KC; ++cc) {
                const float* xr = &Xs[(ch * KC + cc) * TM + r0];
                unsigned long long x2[4];
#pragma unroll
                for (int i = 0; i < 4; ++i) {
                    float2 v = *(const float2*)(xr + 2 * i);
                    x2[i] = pack2(v.x, v.y);
                }
                const float* wr = &Ws[cc * TN + tn];
#pragma unroll
                for (int j = 0; j < 8; ++j) {
                    float wv = wr[16 * j];
                    unsigned long long w2 = pack2(wv, wv);
#pragma unroll
                    for (int i = 0; i < 4; ++i) fma2(acc[i][j], x2[i], w2);
                }
            }
        }

        // ---- scatter prep: per-row target + scale, per-col bias ----
        __syncthreads();   // previous kg's scatter reads done before overwrite
        if (tid < TM) {
            int gv = v0 + tid;
            int u = 0; float sc = 0.0f;
            if (gv < N_LOW) {
                u  = neigh[gv * KNEIGH + kg];
                sc = g_inv[u];
            }
            u_s[tid]  = u;
            sc_s[tid] = sc;
        } else {
            int n = tid - TM;   // 0..127
            b_s[n] = bias[kg * C_OUTX + n];
        }
        __syncthreads();

        // ---- atomic scatter: out[b][n][u] += (acc + bias) * inv_count ----
#pragma unroll
        for (int i = 0; i < 4; ++i) {
            const int ra = r0 + 2 * i;
            const int rb = ra + 1;
            const int   ua = u_s[ra]; const float sa = sc_s[ra];
            const int   ub = u_s[rb]; const float sb = sc_s[rb];
            const bool  va = (v0 + ra) < N_LOW;
            const bool  vb = (v0 + rb) < N_LOW;
#pragma unroll
            for (int j = 0; j < 8; ++j) {
                float lo, hi;
                unpack2(acc[i][j], lo, hi);
                const int   n  = tn + 16 * j;
                const float bv = b_s[n];
                if (va) atomicAdd(ob + (size_t)n * N_UP + ua, (lo + bv) * sa);
                if (vb) atomicAdd(ob + (size_t)n * N_UP + ub, (hi + bv) * sb);
            }
        }
    }
}

// ---------------------------------------------------------------------------
// launch
// ---------------------------------------------------------------------------
extern "C" void kernel_launch(void* const* d_in, const int* in_sizes, int n_in,
                              void* d_out, int out_size)
{
    const float* x     = (const float*)d_in[0];   // [16,256,10242]
    const float* w     = (const float*)d_in[1];   // [256,896]
    const float* bias  = (const float*)d_in[2];   // [896]
    const int*   neigh = (const int*)  d_in[3];   // [71694]
    float*       out   = (float*)d_out;           // [16,128,40962]

    static bool attr_set = false;
    if (!attr_set) {
        cudaFuncSetAttribute(fused_gemm_scatter_k,
                             cudaFuncAttributeMaxDynamicSharedMemorySize,
                             (int)SMEM_BYTES);
        attr_set = true;
    }

    cudaMemsetAsync(d_out, 0, (size_t)out_size * sizeof(float));

    zero_counts_k<<<(N_UP + 255) / 256, 256>>>();
    count_k<<<(N_LOW * KNEIGH + 255) / 256, 256>>>(neigh);
    invert_k<<<(N_UP + 255) / 256, 256>>>();

    dim3 grid(VTILES, BB);
    fused_gemm_scatter_k<<<grid, NTHREADS, SMEM_BYTES>>>(x, w, bias, neigh, out);
}

// round 5
// speedup vs baseline: 2.5366x; 2.5366x over previous
#include <cuda_runtime.h>
#include <cuda_bf16.h>
#include <cstdint>

// ---------------- problem constants ----------------
#define BB      16
#define C_INX   256
#define C_OUTX  128
#define N_LOW   10242
#define N_UP    40962
#define KNEIGH  7
#define KF      896               // KNEIGH * C_OUTX
#define NFLAT   (N_LOW * KNEIGH)  // 71694
#define TM      128
#define NTH     256
#define VTILES  81

// ---------------- phase-1 SMEM layout ----------------
// A: [128 m][256 k] bf16, row stride 528B (512 data + 16 pad) -> conflict-free ldmatrix
#define A_HI     0
#define A_STRIDE 528
#define A_BYTES  (128 * A_STRIDE)       // 67584
#define A_LO     A_BYTES
// B: double-buffered K-chunks of 64: [var hi/lo][128 n][64 k] stride 144B
#define B_OFF    (2 * A_BYTES)          // 135168
#define B_STRIDE 144
#define B_VAR    (128 * B_STRIDE)       // 18432
#define B_BUF    (2 * B_VAR)            // 36864
#define BIAS_OFF (B_OFF + 2 * B_BUF)    // 208896
#define SMEM_ALLOC (BIAS_OFF + KF * 4)  // 212480

// ---------------- device scratch ----------------
__device__ int   g_cnt[N_UP];
__device__ int   g_off[N_UP + 1];
__device__ int   g_pos[N_UP];
__device__ int   g_csr[NFLAT];
__device__ float g_inv[N_UP];
// W pre-split bf16 hi/lo, packed [kg][kchunk][var][n 128][k 64] (16KB blocks)
__device__ unsigned char g_wpack[KNEIGH * 4 * 2 * 16384];
// dense intermediate y[f][b][n], f = v*7+kg
__device__ float g_y[(size_t)NFLAT * BB * C_OUTX];

// ---------------- PTX helpers (all plain sm_80+, no 'a' features) ----------------
__device__ __forceinline__ uint32_t smem_u32(const void* p) {
    uint32_t a;
    asm("{ .reg .u64 t; cvta.to.shared.u64 t, %1; cvt.u32.u64 %0, t; }" : "=r"(a) : "l"(p));
    return a;
}
#define LDSM4(r, addr) \
    asm volatile("ldmatrix.sync.aligned.m8n8.x4.shared.b16 {%0,%1,%2,%3}, [%4];" \
        : "=r"((r)[0]), "=r"((r)[1]), "=r"((r)[2]), "=r"((r)[3]) : "r"(addr))
#define MMA16816(d, a, b0, b1) \
    asm volatile("mma.sync.aligned.m16n8k16.row.col.f32.bf16.bf16.f32 " \
        "{%0,%1,%2,%3}, {%4,%5,%6,%7}, {%8,%9}, {%0,%1,%2,%3};" \
        : "+f"((d)[0]), "+f"((d)[1]), "+f"((d)[2]), "+f"((d)[3]) \
        : "r"((a)[0]), "r"((a)[1]), "r"((a)[2]), "r"((a)[3]), "r"(b0), "r"(b1))
#define CP16(dst, src) \
    asm volatile("cp.async.cg.shared.global [%0], [%1], 16;" :: "r"(dst), "l"(src))
#define CP_COMMIT() asm volatile("cp.async.commit_group;")
#define CP_WAIT1()  asm volatile("cp.async.wait_group 1;")
#define CP_WAIT0()  asm volatile("cp.async.wait_group 0;")

// ---------------- prep kernels ----------------
__global__ void zero_k() {
    int i = blockIdx.x * blockDim.x + threadIdx.x;
    if (i < N_UP) { g_cnt[i] = 0; g_pos[i] = 0; }
}
__global__ void count_k(const int* __restrict__ neigh) {
    int i = blockIdx.x * blockDim.x + threadIdx.x;
    if (i < NFLAT) atomicAdd(&g_cnt[neigh[i]], 1);
}
__global__ void invert_k() {
    int i = blockIdx.x * blockDim.x + threadIdx.x;
    if (i < N_UP) g_inv[i] = 1.0f / (float)g_cnt[i];
    if (i == 0) g_off[N_UP] = NFLAT;
}
__global__ __launch_bounds__(1024) void scan_k() {
    __shared__ int wsum[32];
    __shared__ int sbase;
    int tid = threadIdx.x;
    if (tid == 0) sbase = 0;
    __syncthreads();
    for (int c0 = 0; c0 < N_UP; c0 += 1024) {
        int i = c0 + tid;
        int v = (i < N_UP) ? g_cnt[i] : 0;
        int s = v;
#pragma unroll
        for (int d = 1; d < 32; d <<= 1) {
            int t = __shfl_up_sync(0xFFFFFFFFu, s, d);
            if ((tid & 31) >= d) s += t;
        }
        if ((tid & 31) == 31) wsum[tid >> 5] = s;
        __syncthreads();
        if (tid < 32) {
            int ws = wsum[tid];
#pragma unroll
            for (int d = 1; d < 32; d <<= 1) {
                int t = __shfl_up_sync(0xFFFFFFFFu, ws, d);
                if (tid >= d) ws += t;
            }
            wsum[tid] = ws;
        }
        __syncthreads();
        int excl = s - v + ((tid >= 32) ? wsum[(tid >> 5) - 1] : 0);
        if (i < N_UP) g_off[i] = sbase + excl;
        int btot = wsum[31];
        __syncthreads();
        if (tid == 0) sbase += btot;
        __syncthreads();
    }
}
__global__ void fill_k(const int* __restrict__ neigh) {
    int i = blockIdx.x * blockDim.x + threadIdx.x;
    if (i < NFLAT) {
        int u = neigh[i];
        int slot = atomicAdd(&g_pos[u], 1);
        g_csr[g_off[u] + slot] = i;
    }
}
// split W -> bf16 hi/lo into packed blocks [kg*4+c][var][n][kk]
__global__ void prep_w_k(const float* __restrict__ w) {
    int idx = blockIdx.x * blockDim.x + threadIdx.x;
    if (idx >= KNEIGH * 4 * 128 * 64) return;
    int kk = idx & 63;
    int n  = (idx >> 6) & 127;
    int c  = (idx >> 13) & 3;
    int kg = idx >> 15;
    float v = w[(size_t)(c * 64 + kk) * KF + kg * C_OUTX + n];
    __nv_bfloat16 hi = __float2bfloat16(v);
    __nv_bfloat16 lo = __float2bfloat16(v - __bfloat162float(hi));
    size_t blk = (size_t)((kg * 4 + c) * 2) * 16384;
    *(__nv_bfloat16*)(g_wpack + blk + n * 128 + kk * 2)         = hi;
    *(__nv_bfloat16*)(g_wpack + blk + 16384 + n * 128 + kk * 2) = lo;
}

// ---------------- phase 1: HMMA GEMM -> y ----------------
__device__ __forceinline__ void issue_chunk(uint32_t sb, int tid, int t, int buf) {
    int kg = t >> 2, c = t & 3;
    const unsigned char* src = g_wpack + (size_t)((kg * 4 + c) * 2) * 16384;
    uint32_t dst = sb + B_OFF + buf * B_BUF;
#pragma unroll
    for (int o = 0; o < 8; ++o) {
        int flat = o * NTH + tid;          // 0..2047
        int var = flat >> 10;
        int n   = (flat >> 3) & 127;
        int seg = flat & 7;
        CP16(dst + var * B_VAR + n * B_STRIDE + seg * 16,
             src + var * 16384 + n * 128 + seg * 16);
    }
}

__global__ __launch_bounds__(NTH, 1)
void gemm_k(const float* __restrict__ x,
            const float* __restrict__ bias)
{
    extern __shared__ __align__(128) char sm[];
    const uint32_t sb = smem_u32(sm);

    const int tid    = threadIdx.x;
    const int wid    = tid >> 5;
    const int lane   = tid & 31;
    const int warp_m = wid & 3;       // 32-row group
    const int warp_n = wid >> 2;      // 64-col group
    const int v0     = blockIdx.x * TM;
    const int b      = blockIdx.y;

    // ---- stage A: x -> bf16 hi/lo, row-major [m][k], padded stride ----
    {
        const float* xb = x + (size_t)b * C_INX * N_LOW;
        const int v = tid & 127;
        const int cstart = (tid >> 7) * 2;     // 0 or 2
        const bool valid = (v0 + v) < N_LOW;
        for (int c = cstart; c < C_INX; c += 4) {
            float f0 = valid ? xb[(size_t)c * N_LOW + v0 + v] : 0.0f;
            float f1 = valid ? xb[(size_t)(c + 1) * N_LOW + v0 + v] : 0.0f;
            __nv_bfloat16 h0 = __float2bfloat16(f0);
            __nv_bfloat16 h1 = __float2bfloat16(f1);
            __nv_bfloat16 l0 = __float2bfloat16(f0 - __bfloat162float(h0));
            __nv_bfloat16 l1 = __float2bfloat16(f1 - __bfloat162float(h1));
            __nv_bfloat162 hp; hp.x = h0; hp.y = h1;
            __nv_bfloat162 lp; lp.x = l0; lp.y = l1;
            *(__nv_bfloat162*)(sm + A_HI + v * A_STRIDE + c * 2) = hp;
            *(__nv_bfloat162*)(sm + A_LO + v * A_STRIDE + c * 2) = lp;
        }
    }
    for (int i = tid; i < KF; i += NTH)
        ((float*)(sm + BIAS_OFF))[i] = bias[i];
    __syncthreads();

    // per-thread ldmatrix base addresses
    const uint32_t aHi = sb + A_HI + (warp_m * 32 + (lane & 15)) * A_STRIDE + (lane >> 4) * 16;
    const uint32_t aLo = aHi + A_BYTES;
    const uint32_t brOff = (uint32_t)(warp_n * 64 + (lane & 7) + ((lane >> 4) & 1) * 8) * B_STRIDE
                         + ((lane >> 3) & 1) * 16;

    float acc[2][8][4];
#pragma unroll
    for (int mi = 0; mi < 2; ++mi)
#pragma unroll
        for (int ni = 0; ni < 8; ++ni)
#pragma unroll
            for (int q = 0; q < 4; ++q) acc[mi][ni][q] = 0.0f;

    issue_chunk(sb, tid, 0, 0);
    CP_COMMIT();

    for (int t = 0; t < 28; ++t) {
        const int kg = t >> 2, c = t & 3, buf = t & 1;
        __syncthreads();                       // prior mma done reading other buffer
        if (t + 1 < 28) { issue_chunk(sb, tid, t + 1, (t + 1) & 1); CP_COMMIT(); CP_WAIT1(); }
        else            { CP_WAIT0(); }
        __syncthreads();                       // chunk t visible

        const uint32_t bHiB = sb + B_OFF + buf * B_BUF + brOff;
        const uint32_t bLoB = bHiB + B_VAR;
        const int cByte = c * 128;

#pragma unroll
        for (int s = 0; s < 4; ++s) {
            const int kb = cByte + s * 32;
            uint32_t ah[2][4], al[2][4], bh[4][4], bl[4][4];
            LDSM4(ah[0], aHi + kb);
            LDSM4(ah[1], aHi + 16 * A_STRIDE + kb);
            LDSM4(al[0], aLo + kb);
            LDSM4(al[1], aLo + 16 * A_STRIDE + kb);
#pragma unroll
            for (int p = 0; p < 4; ++p) {
                LDSM4(bh[p], bHiB + p * (16 * B_STRIDE) + s * 32);
                LDSM4(bl[p], bLoB + p * (16 * B_STRIDE) + s * 32);
            }
#pragma unroll
            for (int ni = 0; ni < 8; ++ni) {
                const uint32_t h0 = bh[ni >> 1][(ni & 1) * 2];
                const uint32_t h1 = bh[ni >> 1][(ni & 1) * 2 + 1];
                const uint32_t l0 = bl[ni >> 1][(ni & 1) * 2];
                const uint32_t l1 = bl[ni >> 1][(ni & 1) * 2 + 1];
                MMA16816(acc[0][ni], ah[0], h0, h1);
                MMA16816(acc[1][ni], ah[1], h0, h1);
                MMA16816(acc[0][ni], al[0], h0, h1);
                MMA16816(acc[1][ni], al[1], h0, h1);
                MMA16816(acc[0][ni], ah[0], l0, l1);
                MMA16816(acc[1][ni], ah[1], l0, l1);
            }
        }

        if (c == 3) {
            // ---- write y for this kg, add bias, reset acc ----
            const float* bs = (const float*)(sm + BIAS_OFF) + kg * C_OUTX;
#pragma unroll
            for (int mi = 0; mi < 2; ++mi) {
                const int g = warp_m * 32 + mi * 16 + (lane >> 2);
                const int v1 = v0 + g;
                const int v2 = v1 + 8;
#pragma unroll
                for (int ni = 0; ni < 8; ++ni) {
                    const int n = warp_n * 64 + ni * 8 + (lane & 3) * 2;
                    const float b0v = bs[n], b1v = bs[n + 1];
                    if (v1 < N_LOW) {
                        float2 o0 = make_float2(acc[mi][ni][0] + b0v, acc[mi][ni][1] + b1v);
                        *(float2*)(g_y + ((size_t)(v1 * KNEIGH + kg) * BB + b) * C_OUTX + n) = o0;
                    }
                    if (v2 < N_LOW) {
                        float2 o1 = make_float2(acc[mi][ni][2] + b0v, acc[mi][ni][3] + b1v);
                        *(float2*)(g_y + ((size_t)(v2 * KNEIGH + kg) * BB + b) * C_OUTX + n) = o1;
                    }
                    acc[mi][ni][0] = 0.0f; acc[mi][ni][1] = 0.0f;
                    acc[mi][ni][2] = 0.0f; acc[mi][ni][3] = 0.0f;
                }
            }
        }
    }
}

// ---------------- phase 2: CSR gather -> out ----------------
__global__ __launch_bounds__(256)
void gather_k(float* __restrict__ out)
{
    __shared__ float ts[128 * 33];
    const int tid  = threadIdx.x;
    const int wid  = tid >> 5;
    const int lane = tid & 31;
    const int u0   = blockIdx.x * 32;
    const int b    = blockIdx.y;

#pragma unroll
    for (int k = 0; k < 4; ++k) {
        const int uu = wid * 4 + k;
        const int u  = u0 + uu;
        float4 a = make_float4(0.f, 0.f, 0.f, 0.f);
        if (u < N_UP) {
            const int s = g_off[u], e = g_off[u + 1];
            const float inv = g_inv[u];
            for (int j = s; j < e; ++j) {
                const int f = g_csr[j];
                const float4 v = *((const float4*)g_y + ((size_t)f * BB + b) * 32 + lane);
                a.x += v.x; a.y += v.y; a.z += v.z; a.w += v.w;
            }
            a.x *= inv; a.y *= inv; a.z *= inv; a.w *= inv;
        }
        const int n = lane * 4;
        ts[(n + 0) * 33 + uu] = a.x;
        ts[(n + 1) * 33 + uu] = a.y;
        ts[(n + 2) * 33 + uu] = a.z;
        ts[(n + 3) * 33 + uu] = a.w;
    }
    __syncthreads();

    float* ob = out + (size_t)b * C_OUTX * N_UP;
    const bool full = (u0 + 32) <= N_UP;
#pragma unroll
    for (int i = 0; i < 8; ++i) {
        const int idx = i * 256 + tid;     // 2048 float2
        const int n   = idx >> 4;
        const int seg = idx & 15;
        const int u   = u0 + seg * 2;
        const float w0 = ts[n * 33 + seg * 2];
        const float w1 = ts[n * 33 + seg * 2 + 1];
        if (full) {
            *(float2*)(ob + (size_t)n * N_UP + u) = make_float2(w0, w1);
        } else {
            if (u < N_UP)     ob[(size_t)n * N_UP + u]     = w0;
            if (u + 1 < N_UP) ob[(size_t)n * N_UP + u + 1] = w1;
        }
    }
}

// ---------------- launch ----------------
extern "C" void kernel_launch(void* const* d_in, const int* in_sizes, int n_in,
                              void* d_out, int out_size)
{
    const float* x     = (const float*)d_in[0];   // [16,256,10242]
    const float* w     = (const float*)d_in[1];   // [256,896]
    const float* bias  = (const float*)d_in[2];   // [896]
    const int*   neigh = (const int*)  d_in[3];   // [71694]
    float*       out   = (float*)d_out;           // [16,128,40962]

    static bool attr_set = false;
    if (!attr_set) {
        cudaFuncSetAttribute(gemm_k,
                             cudaFuncAttributeMaxDynamicSharedMemorySize,
                             (int)SMEM_ALLOC);
        attr_set = true;
    }

    zero_k<<<(N_UP + 255) / 256, 256>>>();
    count_k<<<(NFLAT + 255) / 256, 256>>>(neigh);
    invert_k<<<(N_UP + 255) / 256, 256>>>();
    scan_k<<<1, 1024>>>();
    fill_k<<<(NFLAT + 255) / 256, 256>>>(neigh);
    prep_w_k<<<(KNEIGH * 4 * 128 * 64 + 255) / 256, 256>>>(w);

    dim3 grid1(VTILES, BB);
    gemm_k<<<grid1, NTH, SMEM_ALLOC>>>(x, bias);

    dim3 grid2((N_UP + 31) / 32, BB);
    gather_k<<<grid2, 256>>>(out);
}

// round 6
// speedup vs baseline: 4.5586x; 1.7972x over previous
#include <cuda_runtime.h>
#include <cuda_fp16.h>
#include <cstdint>

// ---------------- problem constants ----------------
#define BB      16
#define C_OUTX  128
#define C_INX   256
#define N_LOW   10242
#define N_UP    40962
#define KNEIGH  7
#define KF      896               // KNEIGH * C_OUTX
#define NFLAT   (N_LOW * KNEIGH)  // 71694
#define TM      128
#define NTH     256
#define VTILES  81

// ---------------- phase-1 SMEM layout ----------------
// A: [128 m][256 k] fp16, row stride 528B (512 data + 16 pad)
#define A_OFF    0
#define A_STRIDE 528
#define A_BYTES  (128 * A_STRIDE)       // 67584
// B: double-buffered K-chunks of 64: [128 n][64 k] fp16, stride 144B
#define B_OFF    A_BYTES
#define B_STRIDE 144
#define B_BUF    (128 * B_STRIDE)       // 18432
#define BIAS_OFF (B_OFF + 2 * B_BUF)    // 104448
#define SMEM_ALLOC (BIAS_OFF + KF * 4)  // 108032

#define SCAN_NB  ((N_UP + 255) / 256)   // 161

// ---------------- device scratch ----------------
__device__ int   g_cnt[N_UP];
__device__ int   g_off[N_UP + 1];
__device__ int   g_pos[N_UP];
__device__ int   g_csr[NFLAT];
__device__ float g_inv[N_UP];
__device__ int   g_bsum[SCAN_NB];
__device__ int   g_bbase[SCAN_NB];
// W fp16, packed [kg][kchunk][n 128][k 64]
__device__ __half g_wpack[KNEIGH * 4 * 128 * 64];
// dense intermediate y[f][b][n] fp16, f = v*7+kg
__device__ __half g_y[(size_t)NFLAT * BB * C_OUTX];

// ---------------- PTX helpers (plain sm_80+) ----------------
__device__ __forceinline__ uint32_t smem_u32(const void* p) {
    uint32_t a;
    asm("{ .reg .u64 t; cvta.to.shared.u64 t, %1; cvt.u32.u64 %0, t; }" : "=r"(a) : "l"(p));
    return a;
}
#define LDSM4(r, addr) \
    asm volatile("ldmatrix.sync.aligned.m8n8.x4.shared.b16 {%0,%1,%2,%3}, [%4];" \
        : "=r"((r)[0]), "=r"((r)[1]), "=r"((r)[2]), "=r"((r)[3]) : "r"(addr))
#define MMA16816(d, a, b0, b1) \
    asm volatile("mma.sync.aligned.m16n8k16.row.col.f32.f16.f16.f32 " \
        "{%0,%1,%2,%3}, {%4,%5,%6,%7}, {%8,%9}, {%0,%1,%2,%3};" \
        : "+f"((d)[0]), "+f"((d)[1]), "+f"((d)[2]), "+f"((d)[3]) \
        : "r"((a)[0]), "r"((a)[1]), "r"((a)[2]), "r"((a)[3]), "r"(b0), "r"(b1))
#define CP16(dst, src) \
    asm volatile("cp.async.cg.shared.global [%0], [%1], 16;" :: "r"(dst), "l"(src))
#define CP_COMMIT() asm volatile("cp.async.commit_group;")
#define CP_WAIT1()  asm volatile("cp.async.wait_group 1;")
#define CP_WAIT0()  asm volatile("cp.async.wait_group 0;")

// ---------------- prep kernels ----------------
__global__ void zero_k() {
    int i = blockIdx.x * blockDim.x + threadIdx.x;
    if (i < N_UP) { g_cnt[i] = 0; g_pos[i] = 0; }
}
__global__ void count_k(const int* __restrict__ neigh) {
    int i = blockIdx.x * blockDim.x + threadIdx.x;
    if (i < NFLAT) atomicAdd(&g_cnt[neigh[i]], 1);
}
__global__ void invert_k() {
    int i = blockIdx.x * blockDim.x + threadIdx.x;
    if (i < N_UP) g_inv[i] = 1.0f / (float)g_cnt[i];
    if (i == 0) g_off[N_UP] = NFLAT;
}

// ---- 3-stage block scan of g_cnt -> g_off (exclusive) ----
__global__ __launch_bounds__(256) void scan_sum_k() {
    const int tid = threadIdx.x;
    const int i = blockIdx.x * 256 + tid;
    int v = (i < N_UP) ? g_cnt[i] : 0;
#pragma unroll
    for (int d = 16; d > 0; d >>= 1) v += __shfl_down_sync(0xFFFFFFFFu, v, d);
    __shared__ int ws[8];
    if ((tid & 31) == 0) ws[tid >> 5] = v;
    __syncthreads();
    if (tid == 0) {
        int s = 0;
#pragma unroll
        for (int j = 0; j < 8; ++j) s += ws[j];
        g_bsum[blockIdx.x] = s;
    }
}
__global__ __launch_bounds__(256) void scan_base_k() {
    const int tid = threadIdx.x;
    int v = (tid < SCAN_NB) ? g_bsum[tid] : 0;
    int s = v;
#pragma unroll
    for (int d = 1; d < 32; d <<= 1) {
        int t = __shfl_up_sync(0xFFFFFFFFu, s, d);
        if ((tid & 31) >= d) s += t;
    }
    __shared__ int ws[8];
    if ((tid & 31) == 31) ws[tid >> 5] = s;
    __syncthreads();
    if (tid < 32) {
        int w = (tid < 8) ? ws[tid] : 0;
#pragma unroll
        for (int d = 1; d < 8; d <<= 1) {
            int t = __shfl_up_sync(0xFFFFFFFFu, w, d);
            if (tid >= d) w += t;
        }
        if (tid < 8) ws[tid] = w;
    }
    __syncthreads();
    int incl = s + ((tid >= 32) ? ws[(tid >> 5) - 1] : 0);
    if (tid < SCAN_NB) g_bbase[tid] = incl - v;   // exclusive base
}
__global__ __launch_bounds__(256) void scan_fill_k() {
    const int tid = threadIdx.x;
    const int i = blockIdx.x * 256 + tid;
    int v = (i < N_UP) ? g_cnt[i] : 0;
    int s = v;
#pragma unroll
    for (int d = 1; d < 32; d <<= 1) {
        int t = __shfl_up_sync(0xFFFFFFFFu, s, d);
        if ((tid & 31) >= d) s += t;
    }
    __shared__ int ws[8];
    if ((tid & 31) == 31) ws[tid >> 5] = s;
    __syncthreads();
    if (tid < 32) {
        int w = (tid < 8) ? ws[tid] : 0;
#pragma unroll
        for (int d = 1; d < 8; d <<= 1) {
            int t = __shfl_up_sync(0xFFFFFFFFu, w, d);
            if (tid >= d) w += t;
        }
        if (tid < 8) ws[tid] = w;
    }
    __syncthreads();
    int excl = s - v + ((tid >= 32) ? ws[(tid >> 5) - 1] : 0);
    if (i < N_UP) g_off[i] = g_bbase[blockIdx.x] + excl;
}

__global__ void fill_k(const int* __restrict__ neigh) {
    int i = blockIdx.x * blockDim.x + threadIdx.x;
    if (i < NFLAT) {
        int u = neigh[i];
        int slot = atomicAdd(&g_pos[u], 1);
        g_csr[g_off[u] + slot] = i;
    }
}
// W -> fp16 packed [kg*4+c][n][kk]
__global__ void prep_w_k(const float* __restrict__ w) {
    int idx = blockIdx.x * blockDim.x + threadIdx.x;
    if (idx >= KNEIGH * 4 * 128 * 64) return;
    int kk = idx & 63;
    int n  = (idx >> 6) & 127;
    int c  = (idx >> 13) & 3;
    int kg = idx >> 15;
    float v = w[(size_t)(c * 64 + kk) * KF + kg * C_OUTX + n];
    g_wpack[(size_t)(kg * 4 + c) * 8192 + n * 64 + kk] = __float2half_rn(v);
}

// ---------------- phase 1: fp16 HMMA GEMM -> y (fp16) ----------------
__device__ __forceinline__ void issue_chunk(uint32_t sb, int tid, int t, int buf) {
    const __half* src = g_wpack + (size_t)t * 8192;
    uint32_t dst = sb + B_OFF + buf * B_BUF;
#pragma unroll
    for (int o = 0; o < 4; ++o) {
        int flat = o * NTH + tid;          // 0..1023 x 16B
        int n   = flat >> 3;
        int seg = flat & 7;
        CP16(dst + n * B_STRIDE + seg * 16, (const char*)src + n * 128 + seg * 16);
    }
}

__global__ __launch_bounds__(NTH, 2)
void gemm_k(const float* __restrict__ x,
            const float* __restrict__ bias)
{
    extern __shared__ __align__(128) char sm[];
    const uint32_t sb = smem_u32(sm);

    const int tid    = threadIdx.x;
    const int wid    = tid >> 5;
    const int lane   = tid & 31;
    const int warp_m = wid & 3;       // 32-row group
    const int warp_n = wid >> 2;      // 64-col group
    const int v0     = blockIdx.x * TM;
    const int b      = blockIdx.y;

    // ---- stage A: x -> fp16, row-major [m][k], padded stride ----
    {
        const float* xb = x + (size_t)b * C_INX * N_LOW;
        const int v = tid & 127;
        const int cstart = (tid >> 7) * 2;     // 0 or 2
        const bool valid = (v0 + v) < N_LOW;
        for (int c = cstart; c < C_INX; c += 4) {
            float f0 = valid ? xb[(size_t)c * N_LOW + v0 + v] : 0.0f;
            float f1 = valid ? xb[(size_t)(c + 1) * N_LOW + v0 + v] : 0.0f;
            *(__half2*)(sm + A_OFF + v * A_STRIDE + c * 2) = __floats2half2_rn(f0, f1);
        }
    }
    for (int i = tid; i < KF; i += NTH)
        ((float*)(sm + BIAS_OFF))[i] = bias[i];
    __syncthreads();

    const uint32_t aB = sb + A_OFF + (warp_m * 32 + (lane & 15)) * A_STRIDE + (lane >> 4) * 16;
    const uint32_t brOff = (uint32_t)(warp_n * 64 + (lane & 7) + ((lane >> 4) & 1) * 8) * B_STRIDE
                         + ((lane >> 3) & 1) * 16;

    float acc[2][8][4];
#pragma unroll
    for (int mi = 0; mi < 2; ++mi)
#pragma unroll
        for (int ni = 0; ni < 8; ++ni)
#pragma unroll
            for (int q = 0; q < 4; ++q) acc[mi][ni][q] = 0.0f;

    issue_chunk(sb, tid, 0, 0);
    CP_COMMIT();

    for (int t = 0; t < 28; ++t) {
        const int kg = t >> 2, c = t & 3, buf = t & 1;
        __syncthreads();                       // prior mma done reading other buffer
        if (t + 1 < 28) { issue_chunk(sb, tid, t + 1, (t + 1) & 1); CP_COMMIT(); CP_WAIT1(); }
        else            { CP_WAIT0(); }
        __syncthreads();                       // chunk t visible

        const uint32_t bB = sb + B_OFF + buf * B_BUF + brOff;
        const int cByte = c * 128;

#pragma unroll
        for (int s = 0; s < 4; ++s) {
            const int kb = cByte + s * 32;
            uint32_t af[2][4], bf[4][4];
            LDSM4(af[0], aB + kb);
            LDSM4(af[1], aB + 16 * A_STRIDE + kb);
#pragma unroll
            for (int p = 0; p < 4; ++p)
                LDSM4(bf[p], bB + p * (16 * B_STRIDE) + s * 32);
#pragma unroll
            for (int ni = 0; ni < 8; ++ni) {
                const uint32_t b0 = bf[ni >> 1][(ni & 1) * 2];
                const uint32_t b1 = bf[ni >> 1][(ni & 1) * 2 + 1];
                MMA16816(acc[0][ni], af[0], b0, b1);
                MMA16816(acc[1][ni], af[1], b0, b1);
            }
        }

        if (c == 3) {
            // ---- write y (fp16) for this kg, add bias, reset acc ----
            const float* bs = (const float*)(sm + BIAS_OFF) + kg * C_OUTX;
#pragma unroll
            for (int mi = 0; mi < 2; ++mi) {
                const int g = warp_m * 32 + mi * 16 + (lane >> 2);
                const int v1 = v0 + g;
                const int v2 = v1 + 8;
#pragma unroll
                for (int ni = 0; ni < 8; ++ni) {
                    const int n = warp_n * 64 + ni * 8 + (lane & 3) * 2;
                    const float b0v = bs[n], b1v = bs[n + 1];
                    if (v1 < N_LOW) {
                        *(__half2*)(g_y + ((size_t)(v1 * KNEIGH + kg) * BB + b) * C_OUTX + n)
                            = __floats2half2_rn(acc[mi][ni][0] + b0v, acc[mi][ni][1] + b1v);
                    }
                    if (v2 < N_LOW) {
                        *(__half2*)(g_y + ((size_t)(v2 * KNEIGH + kg) * BB + b) * C_OUTX + n)
                            = __floats2half2_rn(acc[mi][ni][2] + b0v, acc[mi][ni][3] + b1v);
                    }
                    acc[mi][ni][0] = 0.0f; acc[mi][ni][1] = 0.0f;
                    acc[mi][ni][2] = 0.0f; acc[mi][ni][3] = 0.0f;
                }
            }
        }
    }
}

// ---------------- phase 2: CSR gather -> out ----------------
__global__ __launch_bounds__(256)
void gather_k(float* __restrict__ out)
{
    __shared__ float ts[128 * 33];
    const int tid  = threadIdx.x;
    const int wid  = tid >> 5;
    const int lane = tid & 31;
    const int u0   = blockIdx.x * 32;
    const int b    = blockIdx.y;

#pragma unroll
    for (int k = 0; k < 4; ++k) {
        const int uu = wid * 4 + k;
        const int u  = u0 + uu;
        float4 a = make_float4(0.f, 0.f, 0.f, 0.f);
        if (u < N_UP) {
            const int s = g_off[u], e = g_off[u + 1];
            const float inv = g_inv[u];
            for (int j = s; j < e; ++j) {
                const int f = g_csr[j];
                // 8 B per lane = 4 halves (n = lane*4 .. lane*4+3)
                const float2 rv = *((const float2*)(g_y + ((size_t)f * BB + b) * C_OUTX) + lane);
                const float2 p0 = __half22float2(*(const __half2*)&rv.x);
                const float2 p1 = __half22float2(*(const __half2*)&rv.y);
                a.x += p0.x; a.y += p0.y; a.z += p1.x; a.w += p1.y;
            }
            a.x *= inv; a.y *= inv; a.z *= inv; a.w *= inv;
        }
        const int n = lane * 4;
        ts[(n + 0) * 33 + uu] = a.x;
        ts[(n + 1) * 33 + uu] = a.y;
        ts[(n + 2) * 33 + uu] = a.z;
        ts[(n + 3) * 33 + uu] = a.w;
    }
    __syncthreads();

    float* ob = out + (size_t)b * C_OUTX * N_UP;
    const bool full = (u0 + 32) <= N_UP;
#pragma unroll
    for (int i = 0; i < 8; ++i) {
        const int idx = i * 256 + tid;     // 2048 float2
        const int n   = idx >> 4;
        const int seg = idx & 15;
        const int u   = u0 + seg * 2;
        const float w0 = ts[n * 33 + seg * 2];
        const float w1 = ts[n * 33 + seg * 2 + 1];
        if (full) {
            *(float2*)(ob + (size_t)n * N_UP + u) = make_float2(w0, w1);
        } else {
            if (u < N_UP)     ob[(size_t)n * N_UP + u]     = w0;
            if (u + 1 < N_UP) ob[(size_t)n * N_UP + u + 1] = w1;
        }
    }
}

// ---------------- launch ----------------
extern "C" void kernel_launch(void* const* d_in, const int* in_sizes, int n_in,
                              void* d_out, int out_size)
{
    const float* x     = (const float*)d_in[0];   // [16,256,10242]
    const float* w     = (const float*)d_in[1];   // [256,896]
    const float* bias  = (const float*)d_in[2];   // [896]
    const int*   neigh = (const int*)  d_in[3];   // [71694]
    float*       out   = (float*)d_out;           // [16,128,40962]

    static bool attr_set = false;
    if (!attr_set) {
        cudaFuncSetAttribute(gemm_k,
                             cudaFuncAttributeMaxDynamicSharedMemorySize,
                             (int)SMEM_ALLOC);
        attr_set = true;
    }

    zero_k<<<(N_UP + 255) / 256, 256>>>();
    count_k<<<(NFLAT + 255) / 256, 256>>>(neigh);
    invert_k<<<(N_UP + 255) / 256, 256>>>();
    scan_sum_k<<<SCAN_NB, 256>>>();
    scan_base_k<<<1, 256>>>();
    scan_fill_k<<<SCAN_NB, 256>>>();
    fill_k<<<(NFLAT + 255) / 256, 256>>>(neigh);
    prep_w_k<<<(KNEIGH * 4 * 128 * 64 + 255) / 256, 256>>>(w);

    dim3 grid1(VTILES, BB);
    gemm_k<<<grid1, NTH, SMEM_ALLOC>>>(x, bias);

    dim3 grid2((N_UP + 31) / 32, BB);
    gather_k<<<grid2, 256>>>(out);
}

// round 8
// speedup vs baseline: 5.6338x; 1.2359x over previous
#include <cuda_runtime.h>
#include <cuda_fp16.h>
#include <cstdint>

// ---------------- problem constants ----------------
#define BB      16
#define C_OUTX  128
#define C_INX   256
#define N_LOW   10242
#define N_UP    40962
#define KNEIGH  7
#define KF      896               // KNEIGH * C_OUTX
#define NFLAT   (N_LOW * KNEIGH)  // 71694
#define TM      128
#define NTH     256
#define VTILES  81

// ---------------- phase-1 SMEM layout ----------------
// A: [128 m][256 k] fp16, row stride 528B (512 data + 16 pad)
#define A_OFF    0
#define A_STRIDE 528
#define A_BYTES  (128 * A_STRIDE)       // 67584
// B: double-buffered K-chunks of 64: [128 n][64 k] fp16, stride 144B
#define B_OFF    A_BYTES
#define B_STRIDE 144
#define B_BUF    (128 * B_STRIDE)       // 18432
#define BIAS_OFF (B_OFF + 2 * B_BUF)    // 104448
#define SMEM_ALLOC (BIAS_OFF + KF * 4)  // 108032

#define SCAN_NB  ((N_UP + 255) / 256)   // 161

// ---------------- device scratch ----------------
__device__ int   g_cnt[N_UP];
__device__ int   g_off[N_UP + 1];
__device__ int   g_pos[N_UP];
__device__ int   g_csr[NFLAT];
__device__ float g_inv[N_UP];
__device__ int   g_bsum[SCAN_NB];
__device__ int   g_bbase[SCAN_NB];
// W fp16, packed [kg][kchunk][n 128][k 64]
__device__ __half g_wpack[KNEIGH * 4 * 128 * 64];
// dense intermediate y[f][b][pi(n)] fp16, f = v*7+kg  (n permuted, see epilogue)
__device__ __half g_y[(size_t)NFLAT * BB * C_OUTX];

// ---------------- PTX helpers (plain sm_80+) ----------------
__device__ __forceinline__ uint32_t smem_u32(const void* p) {
    uint32_t a;
    asm("{ .reg .u64 t; cvta.to.shared.u64 t, %1; cvt.u32.u64 %0, t; }" : "=r"(a) : "l"(p));
    return a;
}
#define LDSM4(r, addr) \
    asm volatile("ldmatrix.sync.aligned.m8n8.x4.shared.b16 {%0,%1,%2,%3}, [%4];" \
        : "=r"((r)[0]), "=r"((r)[1]), "=r"((r)[2]), "=r"((r)[3]) : "r"(addr))
#define MMA16816(d, a, b0, b1) \
    asm volatile("mma.sync.aligned.m16n8k16.row.col.f32.f16.f16.f32 " \
        "{%0,%1,%2,%3}, {%4,%5,%6,%7}, {%8,%9}, {%0,%1,%2,%3};" \
        : "+f"((d)[0]), "+f"((d)[1]), "+f"((d)[2]), "+f"((d)[3]) \
        : "r"((a)[0]), "r"((a)[1]), "r"((a)[2]), "r"((a)[3]), "r"(b0), "r"(b1))
#define CP16(dst, src) \
    asm volatile("cp.async.cg.shared.global [%0], [%1], 16;" :: "r"(dst), "l"(src))
#define CP_COMMIT() asm volatile("cp.async.commit_group;")
#define CP_WAIT1()  asm volatile("cp.async.wait_group 1;")
#define CP_WAIT0()  asm volatile("cp.async.wait_group 0;")

// ---------------- prep kernels ----------------
__global__ void zero_k() {
    int i = blockIdx.x * blockDim.x + threadIdx.x;
    if (i < N_UP) { g_cnt[i] = 0; g_pos[i] = 0; }
}
__global__ void count_k(const int* __restrict__ neigh) {
    int i = blockIdx.x * blockDim.x + threadIdx.x;
    if (i < NFLAT) atomicAdd(&g_cnt[neigh[i]], 1);
}

// ---- 3-stage block scan of g_cnt -> g_off (exclusive); also g_inv ----
__global__ __launch_bounds__(256) void scan_sum_k() {
    const int tid = threadIdx.x;
    const int i = blockIdx.x * 256 + tid;
    int v = (i < N_UP) ? g_cnt[i] : 0;
#pragma unroll
    for (int d = 16; d > 0; d >>= 1) v += __shfl_down_sync(0xFFFFFFFFu, v, d);
    __shared__ int ws[8];
    if ((tid & 31) == 0) ws[tid >> 5] = v;
    __syncthreads();
    if (tid == 0) {
        int s = 0;
#pragma unroll
        for (int j = 0; j < 8; ++j) s += ws[j];
        g_bsum[blockIdx.x] = s;
    }
}
__global__ __launch_bounds__(256) void scan_base_k() {
    const int tid = threadIdx.x;
    int v = (tid < SCAN_NB) ? g_bsum[tid] : 0;
    int s = v;
#pragma unroll
    for (int d = 1; d < 32; d <<= 1) {
        int t = __shfl_up_sync(0xFFFFFFFFu, s, d);
        if ((tid & 31) >= d) s += t;
    }
    __shared__ int ws[8];
    if ((tid & 31) == 31) ws[tid >> 5] = s;
    __syncthreads();
    if (tid < 32) {
        int w = (tid < 8) ? ws[tid] : 0;
#pragma unroll
        for (int d = 1; d < 8; d <<= 1) {
            int t = __shfl_up_sync(0xFFFFFFFFu, w, d);
            if (tid >= d) w += t;
        }
        if (tid < 8) ws[tid] = w;
    }
    __syncthreads();
    int incl = s + ((tid >= 32) ? ws[(tid >> 5) - 1] : 0);
    if (tid < SCAN_NB) g_bbase[tid] = incl - v;   // exclusive base
    if (tid == 0) g_off[N_UP] = NFLAT;
}
__global__ __launch_bounds__(256) void scan_fill_k() {
    const int tid = threadIdx.x;
    const int i = blockIdx.x * 256 + tid;
    int v = (i < N_UP) ? g_cnt[i] : 0;
    int s = v;
#pragma unroll
    for (int d = 1; d < 32; d <<= 1) {
        int t = __shfl_up_sync(0xFFFFFFFFu, s, d);
        if ((tid & 31) >= d) s += t;
    }
    __shared__ int ws[8];
    if ((tid & 31) == 31) ws[tid >> 5] = s;
    __syncthreads();
    if (tid < 32) {
        int w = (tid < 8) ? ws[tid] : 0;
#pragma unroll
        for (int d = 1; d < 8; d <<= 1) {
            int t = __shfl_up_sync(0xFFFFFFFFu, w, d);
            if (tid >= d) w += t;
        }
        if (tid < 8) ws[tid] = w;
    }
    __syncthreads();
    int excl = s - v + ((tid >= 32) ? ws[(tid >> 5) - 1] : 0);
    if (i < N_UP) {
        g_off[i] = g_bbase[blockIdx.x] + excl;
        g_inv[i] = 1.0f / (float)v;
    }
}

__global__ void fill_k(const int* __restrict__ neigh) {
    int i = blockIdx.x * blockDim.x + threadIdx.x;
    if (i < NFLAT) {
        int u = neigh[i];
        int slot = atomicAdd(&g_pos[u], 1);
        g_csr[g_off[u] + slot] = i;
    }
}
// W -> fp16 packed [kg*4+c][n][kk]
__global__ void prep_w_k(const float* __restrict__ w) {
    int idx = blockIdx.x * blockDim.x + threadIdx.x;
    if (idx >= KNEIGH * 4 * 128 * 64) return;
    int kk = idx & 63;
    int n  = (idx >> 6) & 127;
    int c  = (idx >> 13) & 3;
    int kg = idx >> 15;
    float v = w[(size_t)(c * 64 + kk) * KF + kg * C_OUTX + n];
    g_wpack[(size_t)(kg * 4 + c) * 8192 + n * 64 + kk] = __float2half_rn(v);
}

// ---------------- phase 1: fp16 HMMA GEMM -> y (fp16, permuted n) ----------------
__device__ __forceinline__ void issue_chunk(uint32_t sb, int tid, int t, int buf) {
    const __half* src = g_wpack + (size_t)t * 8192;
    uint32_t dst = sb + B_OFF + buf * B_BUF;
#pragma unroll
    for (int o = 0; o < 4; ++o) {
        int flat = o * NTH + tid;          // 0..1023 x 16B
        int n   = flat >> 3;
        int seg = flat & 7;
        CP16(dst + n * B_STRIDE + seg * 16, (const char*)src + n * 128 + seg * 16);
    }
}

__device__ __forceinline__ uint32_t h2pack(float a, float b) {
    __half2 h = __floats2half2_rn(a, b);
    return *(uint32_t*)&h;
}

__global__ __launch_bounds__(NTH, 2)
void gemm_k(const float* __restrict__ x,
            const float* __restrict__ bias)
{
    extern __shared__ __align__(128) char sm[];
    const uint32_t sb = smem_u32(sm);

    const int tid    = threadIdx.x;
    const int wid    = tid >> 5;
    const int lane   = tid & 31;
    const int warp_m = wid & 3;       // 32-row group
    const int warp_n = wid >> 2;      // 64-col group
    const int v0     = blockIdx.x * TM;
    const int b      = blockIdx.y;

    // ---- stage A: x -> fp16, row-major [m][k], padded stride ----
    {
        const float* xb = x + (size_t)b * C_INX * N_LOW;
        const int v = tid & 127;
        const int cstart = (tid >> 7) * 2;     // 0 or 2
        const bool valid = (v0 + v) < N_LOW;
        for (int c = cstart; c < C_INX; c += 4) {
            float f0 = valid ? xb[(size_t)c * N_LOW + v0 + v] : 0.0f;
            float f1 = valid ? xb[(size_t)(c + 1) * N_LOW + v0 + v] : 0.0f;
            *(__half2*)(sm + A_OFF + v * A_STRIDE + c * 2) = __floats2half2_rn(f0, f1);
        }
    }
    for (int i = tid; i < KF; i += NTH)
        ((float*)(sm + BIAS_OFF))[i] = bias[i];
    __syncthreads();

    const uint32_t aB = sb + A_OFF + (warp_m * 32 + (lane & 15)) * A_STRIDE + (lane >> 4) * 16;
    const uint32_t brOff = (uint32_t)(warp_n * 64 + (lane & 7) + ((lane >> 4) & 1) * 8) * B_STRIDE
                         + ((lane >> 3) & 1) * 16;

    float acc[2][8][4];
#pragma unroll
    for (int mi = 0; mi < 2; ++mi)
#pragma unroll
        for (int ni = 0; ni < 8; ++ni)
#pragma unroll
            for (int q = 0; q < 4; ++q) acc[mi][ni][q] = 0.0f;

    issue_chunk(sb, tid, 0, 0);
    CP_COMMIT();

    const int qq = lane & 3;       // fragment column quad
    const int rr = lane >> 2;      // fragment row within 8

    for (int t = 0; t < 28; ++t) {
        const int kg = t >> 2, c = t & 3, buf = t & 1;
        __syncthreads();                       // prior mma done reading other buffer
        if (t + 1 < 28) { issue_chunk(sb, tid, t + 1, (t + 1) & 1); CP_COMMIT(); CP_WAIT1(); }
        else            { CP_WAIT0(); }
        __syncthreads();                       // chunk t visible

        const uint32_t bB = sb + B_OFF + buf * B_BUF + brOff;
        const int cByte = c * 128;

#pragma unroll
        for (int s = 0; s < 4; ++s) {
            const int kb = cByte + s * 32;
            uint32_t af[2][4], bf[4][4];
            LDSM4(af[0], aB + kb);
            LDSM4(af[1], aB + 16 * A_STRIDE + kb);
#pragma unroll
            for (int p = 0; p < 4; ++p)
                LDSM4(bf[p], bB + p * (16 * B_STRIDE) + s * 32);
#pragma unroll
            for (int ni = 0; ni < 8; ++ni) {
                const uint32_t b0 = bf[ni >> 1][(ni & 1) * 2];
                const uint32_t b1 = bf[ni >> 1][(ni & 1) * 2 + 1];
                MMA16816(acc[0][ni], af[0], b0, b1);
                MMA16816(acc[1][ni], af[1], b0, b1);
            }
        }

        if (c == 3) {
            // ---- write y (fp16, permuted n) for this kg; coalesced STG.128 ----
            // Permuted layout within each 64-col warp segment (128 B):
            //   byte = h*64 + q*16 + i*4 + e*2, where n = wseg*64 + (h*4+i)*8 + q*2 + e
            const float* bs = (const float*)(sm + BIAS_OFF) + kg * C_OUTX;
#pragma unroll
            for (int mi = 0; mi < 2; ++mi) {
                const int v1 = v0 + warp_m * 32 + mi * 16 + rr;
                const int v2 = v1 + 8;
                uint32_t pk1[8], pk2[8];
#pragma unroll
                for (int ni = 0; ni < 8; ++ni) {
                    const int n = warp_n * 64 + ni * 8 + qq * 2;
                    const float b0v = bs[n], b1v = bs[n + 1];
                    pk1[ni] = h2pack(acc[0 + 0][ni][0], acc[0][ni][0]);  // placeholder (overwritten below)
                    pk1[ni] = h2pack(acc[mi][ni][0] + b0v, acc[mi][ni][1] + b1v);
                    pk2[ni] = h2pack(acc[mi][ni][2] + b0v, acc[mi][ni][3] + b1v);
                    acc[mi][ni][0] = 0.0f; acc[mi][ni][1] = 0.0f;
                    acc[mi][ni][2] = 0.0f; acc[mi][ni][3] = 0.0f;
                }
                if (v1 < N_LOW) {
                    char* row = (char*)(g_y + ((size_t)(v1 * KNEIGH + kg) * BB + b) * C_OUTX);
                    uint4 lo = make_uint4(pk1[0], pk1[1], pk1[2], pk1[3]);
                    uint4 hi = make_uint4(pk1[4], pk1[5], pk1[6], pk1[7]);
                    __stcs((uint4*)(row + warp_n * 128 + qq * 16), lo);
                    __stcs((uint4*)(row + warp_n * 128 + 64 + qq * 16), hi);
                }
                if (v2 < N_LOW) {
                    char* row = (char*)(g_y + ((size_t)(v2 * KNEIGH + kg) * BB + b) * C_OUTX);
                    uint4 lo = make_uint4(pk2[0], pk2[1], pk2[2], pk2[3]);
                    uint4 hi = make_uint4(pk2[4], pk2[5], pk2[6], pk2[7]);
                    __stcs((uint4*)(row + warp_n * 128 + qq * 16), lo);
                    __stcs((uint4*)(row + warp_n * 128 + 64 + qq * 16), hi);
                }
            }
        }
    }
}

// ---------------- phase 2: CSR gather -> out ----------------
__global__ __launch_bounds__(256)
void gather_k(float* __restrict__ out)
{
    __shared__ float ts[128 * 33];
    const int tid  = threadIdx.x;
    const int wid  = tid >> 5;
    const int lane = tid & 31;
    const int u0   = blockIdx.x * 32;
    const int b    = blockIdx.y;

    // un-permute: lane reads halves P = 4*lane .. 4*lane+3 of a y row
    //   -> true n = N0, N0+1, N0+8, N0+9
    const int N0 = (lane >> 4) * 64
                 + (((lane >> 3) & 1) * 4 + 2 * (lane & 1)) * 8
                 + ((lane >> 1) & 3) * 2;

#pragma unroll
    for (int k = 0; k < 4; ++k) {
        const int uu = wid * 4 + k;
        const int u  = u0 + uu;
        float4 a = make_float4(0.f, 0.f, 0.f, 0.f);
        if (u < N_UP) {
            const int s = g_off[u], e = g_off[u + 1];
            const float inv = g_inv[u];
            for (int j = s; j < e; ++j) {
                const int f = g_csr[j];
                const float2 rv = __ldcs((const float2*)(g_y + ((size_t)f * BB + b) * C_OUTX) + lane);
                const float2 p0 = __half22float2(*(const __half2*)&rv.x);
                const float2 p1 = __half22float2(*(const __half2*)&rv.y);
                a.x += p0.x; a.y += p0.y; a.z += p1.x; a.w += p1.y;
            }
            a.x *= inv; a.y *= inv; a.z *= inv; a.w *= inv;
        }
        ts[(N0 + 0) * 33 + uu] = a.x;
        ts[(N0 + 1) * 33 + uu] = a.y;
        ts[(N0 + 8) * 33 + uu] = a.z;
        ts[(N0 + 9) * 33 + uu] = a.w;
    }
    __syncthreads();

    float* ob = out + (size_t)b * C_OUTX * N_UP;
    const bool full = (u0 + 32) <= N_UP;
#pragma unroll
    for (int i = 0; i < 8; ++i) {
        const int idx = i * 256 + tid;     // 2048 float2
        const int n   = idx >> 4;
        const int seg = idx & 15;
        const int u   = u0 + seg * 2;
        const float w0 = ts[n * 33 + seg * 2];
        const float w1 = ts[n * 33 + seg * 2 + 1];
        if (full) {
            __stcs((float2*)(ob + (size_t)n * N_UP + u), make_float2(w0, w1));
        } else {
            if (u < N_UP)     ob[(size_t)n * N_UP + u]     = w0;
            if (u + 1 < N_UP) ob[(size_t)n * N_UP + u + 1] = w1;
        }
    }
}

// ---------------- launch ----------------
extern "C" void kernel_launch(void* const* d_in, const int* in_sizes, int n_in,
                              void* d_out, int out_size)
{
    const float* x     = (const float*)d_in[0];   // [16,256,10242]
    const float* w     = (const float*)d_in[1];   // [256,896]
    const float* bias  = (const float*)d_in[2];   // [896]
    const int*   neigh = (const int*)  d_in[3];   // [71694]
    float*       out   = (float*)d_out;           // [16,128,40962]

    static bool attr_set = false;
    if (!attr_set) {
        cudaFuncSetAttribute(gemm_k,
                             cudaFuncAttributeMaxDynamicSharedMemorySize,
                             (int)SMEM_ALLOC);
        attr_set = true;
    }

    zero_k<<<(N_UP + 255) / 256, 256>>>();
    count_k<<<(NFLAT + 255) / 256, 256>>>(neigh);
    scan_sum_k<<<SCAN_NB, 256>>>();
    scan_base_k<<<1, 256>>>();
    scan_fill_k<<<SCAN_NB, 256>>>();
    fill_k<<<(NFLAT + 255) / 256, 256>>>(neigh);
    prep_w_k<<<(KNEIGH * 4 * 128 * 64 + 255) / 256, 256>>>(w);

    dim3 grid1(VTILES, BB);
    gemm_k<<<grid1, NTH, SMEM_ALLOC>>>(x, bias);

    dim3 grid2((N_UP + 31) / 32, BB);
    gather_k<<<grid2, 256>>>(out);
}